// round 14
// baseline (speedup 1.0000x reference)
#include <cuda_runtime.h>
#include <cuda_fp16.h>
#include <cstdint>
#include <cstddef>

#define N_NODES 50000
#define N_EDGES 800000
#define HID 512
#define ATP 50176             // AT row pitch (>= 50048 touched, 128-aligned)
#define NB_ROW 391            // ceil(50000/128)
#define NB_NODE (NB_ROW * 4)  // 1564 node tiles (6 stages, K=192)
#define NB_UV   (NB_ROW * 8)  // 3128 uv tiles (2 stages, K=64)
#define GRID_GEMM (NB_NODE + NB_UV)
#define NB_EDGE 50000         // 400000 edge pairs / 8 warps per block
#define SMEM_BYTES 65536      // As[2][32*128] + Bs[2][32*128] floats

typedef unsigned long long ull;

// Scratch (device globals; no allocation allowed)
__device__ __align__(32) __half g_Uh[(size_t)N_NODES * HID];
__device__ __align__(32) __half g_Vh[(size_t)N_NODES * HID];
__device__ __align__(16) float  g_AT[(size_t)192 * ATP];   // [nf|pe]^T
__device__ __align__(16) float  g_Wc[64 * HID];            // W1 + W2
__device__ __align__(16) float  g_c0[HID];
__device__ __align__(16) float  g_c1[HID];
__device__ int g_idx64;

__device__ __forceinline__ ull dup2(float x) {
    ull r; asm("mov.b64 %0, {%1,%1};" : "=l"(r) : "f"(x)); return r;
}
__device__ __forceinline__ void unpack2(ull p, float& x, float& y) {
    asm("mov.b64 {%0,%1}, %2;" : "=f"(x), "=f"(y) : "l"(p));
}
#define FFMA2(d, a, b, c) \
    asm("fma.rn.f32x2 %0, %1, %2, %3;" : "=l"(d) : "l"(a), "l"(b), "l"(c))

__device__ __forceinline__ void cp16(uint32_t smem, const void* g) {
    asm volatile("cp.async.cg.shared.global [%0], [%1], 16;"
                 :: "r"(smem), "l"(g));
}
#define CP_COMMIT() asm volatile("cp.async.commit_group;")
#define CP_WAIT0()  asm volatile("cp.async.wait_group 0;")

// 256-bit gather load with L2 evict_last (only legal width for the hint).
struct U8 { unsigned r[8]; };
__device__ __forceinline__ U8 ldg256_el(const void* p) {
    U8 v;
    asm("ld.global.nc.L2::evict_last.v8.b32 {%0,%1,%2,%3,%4,%5,%6,%7}, [%8];"
        : "=r"(v.r[0]), "=r"(v.r[1]), "=r"(v.r[2]), "=r"(v.r[3]),
          "=r"(v.r[4]), "=r"(v.r[5]), "=r"(v.r[6]), "=r"(v.r[7])
        : "l"(p));
    return v;
}

// ---------------------------------------------------------------------------
// Prep: blocks 0..31 -> Wc; 32..47 -> c0/c1 (parallel k-reduction);
//       block 48 -> idx64 detect.
// ---------------------------------------------------------------------------
__global__ void prep_kernel(const float* __restrict__ ef,
                            const float* __restrict__ tte,
                            const float* __restrict__ W,
                            const float* __restrict__ b,
                            const int* __restrict__ ei) {
    const int bi = blockIdx.x, tid = threadIdx.x;
    if (bi < 32) {
        int i = bi * 256 + tid;              // 8192 float4
        float4 a = __ldg((const float4*)(W + 128 * HID) + i);
        float4 c = __ldg((const float4*)(W + 192 * HID) + i);
        a.x += c.x; a.y += c.y; a.z += c.z; a.w += c.w;
        ((float4*)g_Wc)[i] = a;
    } else if (bi < 48) {
        __shared__ float sm0[8][32], sm1[8][32];
        const int kc = tid >> 5, jl = tid & 31;
        const int j0 = (bi - 32) * 32;
        const int j = j0 + jl;
        float s0 = 0.f, s1 = 0.f;
        #pragma unroll 4
        for (int k = kc * 16; k < kc * 16 + 16; k++) {
            float w3 = __ldg(&W[(size_t)(256 + k) * HID + j]);
            s0 += tte[k] * w3;
            s1 += tte[128 + k] * w3 + ef[k] * __ldg(&W[(size_t)k * HID + j]);
        }
        sm0[kc][jl] = s0;
        sm1[kc][jl] = s1;
        __syncthreads();
        if (tid < 32) {
            float a0 = b[j0 + tid], a1 = a0;
            #pragma unroll
            for (int q = 0; q < 8; q++) { a0 += sm0[q][tid]; a1 += sm1[q][tid]; }
            g_c0[j0 + tid] = a0;
            g_c1[j0 + tid] = a1;
        }
    } else if (tid == 0) {
        int is64 = 1;
        #pragma unroll
        for (int i = 1; i < 64; i += 2)
            if (ei[i] != 0) is64 = 0;
        g_idx64 = is64;
    }
}

// ---------------------------------------------------------------------------
// Transpose [nf|pe] -> g_AT[192][ATP]. 32x32 tiles; grid (1563, 6).
// Rows 0..127 = nf^T, rows 128..191 = pe^T.
// ---------------------------------------------------------------------------
__global__ void transpose_kernel(const float* __restrict__ nf,
                                 const float* __restrict__ pe) {
    __shared__ float t[32][33];
    const int tid = threadIdx.x;
    const int tx = tid & 31, ty = tid >> 5;       // ty 0..7
    const int r0 = blockIdx.x * 32, c0 = blockIdx.y * 32;

    #pragma unroll
    for (int j = 0; j < 4; j++) {
        int rr = ty + j * 8;
        int row = r0 + rr;
        float v = 0.f;
        if (row < N_NODES) {
            v = (c0 < 128) ? __ldg(&nf[(size_t)row * 128 + c0 + tx])
                           : __ldg(&pe[(size_t)row * 64 + (c0 - 128) + tx]);
        }
        t[rr][tx] = v;
    }
    __syncthreads();
    #pragma unroll
    for (int j = 0; j < 4; j++) {
        int cc = ty + j * 8;
        g_AT[(size_t)(c0 + cc) * ATP + r0 + tx] = t[tx][cc];
    }
}

// ---------------------------------------------------------------------------
// Pipelined GEMM. 128x128 tile, BK=32 double-buffered via cp.async.
// A streams from g_AT (pre-transposed) -> k-major smem, broadcast LDS reads.
// B streams with XOR pair-swizzle applied on the cp.async DESTINATION, so
// reads keep the proven conflict-free pattern. One __syncthreads per stage;
// stage s+1 loads overlap stage s compute.
// Jobs: bi < NB_NODE -> node (6 stages, AT rows 0..191);
//       else         -> uv   (2 stages, AT rows 128..191).
// ---------------------------------------------------------------------------
__global__ void __launch_bounds__(256, 2)
gemm_kernel(const float* __restrict__ W, float* __restrict__ out) {
    extern __shared__ float smem_dyn[];
    // layout (floats): As0[4096] As1[4096] Bs0[4096] Bs1[4096]
    const uint32_t sbase =
        (uint32_t)__cvta_generic_to_shared(smem_dyn);

    const int tid = threadIdx.x;
    const int lane_ = tid & 31, wid_ = tid >> 5;
    const int tx8 = (((wid_ & 1) << 3) + (lane_ & 7)) * 8;
    const int ty8 = (((wid_ >> 1) << 2) + (lane_ >> 3)) * 8;
    const int n4a = tx8 >> 2;
    const int n4b = n4a + 1;
    const int swA = (n4a ^ ((n4a >> 3) & 1)) << 4;   // byte offset in row
    const int swB = (n4b ^ ((n4b >> 3) & 1)) << 4;

    const int bi = blockIdx.x;
    int row0, col0, nstages, is_node, uv = 0;
    if (bi < NB_NODE) {
        is_node = 1;
        row0 = (bi >> 2) * 128;
        col0 = (bi & 3) * 128;
        nstages = 6;
    } else {
        is_node = 0;
        int u = bi - NB_NODE;
        row0 = (u >> 3) * 128;
        uv   = (u & 7) >> 2;
        col0 = (u & 3) * 128;
        nstages = 2;
    }

    // per-stage source resolution
    auto a_src = [&](int s) -> const float* {
        int kbase = is_node ? s * 32 : 128 + 64 * uv - 64 * uv + 128 - 128;  // placeholder
        return g_AT;  // unused; real logic below
    };
    (void)a_src;

    // cp.async chunk coordinates for this thread (4 A chunks + 4 B chunks)
    // chunk i: idx = i*256+tid; k = idx>>5; q = idx&31
    auto load_stage = [&](int s, int buf) {
        int kbase_a = is_node ? s * 32 : 128 + s * 32;
        const float* Asrc = g_AT + (size_t)kbase_a * ATP + row0;
        const float* Bsrc;
        if (!is_node)       Bsrc = W + (size_t)(128 + 64 * uv + s * 32) * HID + col0;
        else if (s < 4)     Bsrc = W + (size_t)(s * 32) * HID + col0;
        else                Bsrc = g_Wc + (size_t)((s - 4) * 32) * HID + col0;

        uint32_t aBase = sbase + buf * 16384;
        uint32_t bBase = sbase + 32768 + buf * 16384;
        #pragma unroll
        for (int i = 0; i < 4; i++) {
            int idx = i * 256 + tid;
            int k = idx >> 5, q = idx & 31;
            cp16(aBase + (uint32_t)(k * 512 + q * 16),
                 Asrc + (size_t)k * ATP + q * 4);
        }
        #pragma unroll
        for (int i = 0; i < 4; i++) {
            int idx = i * 256 + tid;
            int k = idx >> 5, n4 = idx & 31;
            int n4s = n4 ^ ((n4 >> 3) & 1);
            cp16(bBase + (uint32_t)(k * 512 + n4s * 16),
                 Bsrc + (size_t)k * HID + n4 * 4);
        }
        CP_COMMIT();
    };

    ull acc[32];
    #pragma unroll
    for (int i = 0; i < 32; i++) acc[i] = 0ull;

    load_stage(0, 0);

    for (int s = 0; s < nstages; s++) {
        CP_WAIT0();
        __syncthreads();
        if (s + 1 < nstages) load_stage(s + 1, (s + 1) & 1);

        const float* Aseg = smem_dyn + (s & 1) * 4096;
        const char* bbA = (const char*)(smem_dyn + 8192 + (s & 1) * 4096) + swA;
        const char* bbB = (const char*)(smem_dyn + 8192 + (s & 1) * 4096) + swB;

        #pragma unroll
        for (int k = 0; k < 32; k++) {
            const float4 a0 = *(const float4*)(Aseg + k * 128 + ty8);
            const float4 a1 = *(const float4*)(Aseg + k * 128 + ty8 + 4);
            const ulonglong2 B0 = *(const ulonglong2*)(bbA + (size_t)k * 512);
            const ulonglong2 B1 = *(const ulonglong2*)(bbB + (size_t)k * 512);
            ull aa;
            aa = dup2(a0.x);
            FFMA2(acc[ 0], aa, B0.x, acc[ 0]); FFMA2(acc[ 1], aa, B0.y, acc[ 1]);
            FFMA2(acc[ 2], aa, B1.x, acc[ 2]); FFMA2(acc[ 3], aa, B1.y, acc[ 3]);
            aa = dup2(a0.y);
            FFMA2(acc[ 4], aa, B0.x, acc[ 4]); FFMA2(acc[ 5], aa, B0.y, acc[ 5]);
            FFMA2(acc[ 6], aa, B1.x, acc[ 6]); FFMA2(acc[ 7], aa, B1.y, acc[ 7]);
            aa = dup2(a0.z);
            FFMA2(acc[ 8], aa, B0.x, acc[ 8]); FFMA2(acc[ 9], aa, B0.y, acc[ 9]);
            FFMA2(acc[10], aa, B1.x, acc[10]); FFMA2(acc[11], aa, B1.y, acc[11]);
            aa = dup2(a0.w);
            FFMA2(acc[12], aa, B0.x, acc[12]); FFMA2(acc[13], aa, B0.y, acc[13]);
            FFMA2(acc[14], aa, B1.x, acc[14]); FFMA2(acc[15], aa, B1.y, acc[15]);
            aa = dup2(a1.x);
            FFMA2(acc[16], aa, B0.x, acc[16]); FFMA2(acc[17], aa, B0.y, acc[17]);
            FFMA2(acc[18], aa, B1.x, acc[18]); FFMA2(acc[19], aa, B1.y, acc[19]);
            aa = dup2(a1.y);
            FFMA2(acc[20], aa, B0.x, acc[20]); FFMA2(acc[21], aa, B0.y, acc[21]);
            FFMA2(acc[22], aa, B1.x, acc[22]); FFMA2(acc[23], aa, B1.y, acc[23]);
            aa = dup2(a1.z);
            FFMA2(acc[24], aa, B0.x, acc[24]); FFMA2(acc[25], aa, B0.y, acc[25]);
            FFMA2(acc[26], aa, B1.x, acc[26]); FFMA2(acc[27], aa, B1.y, acc[27]);
            aa = dup2(a1.w);
            FFMA2(acc[28], aa, B0.x, acc[28]); FFMA2(acc[29], aa, B0.y, acc[29]);
            FFMA2(acc[30], aa, B1.x, acc[30]); FFMA2(acc[31], aa, B1.y, acc[31]);
        }
        __syncthreads();
    }

    if (!is_node) {
        __half* Out = uv ? g_Vh : g_Uh;
        #pragma unroll
        for (int m = 0; m < 8; m++) {
            int r = row0 + ty8 + m;
            if (r < N_NODES) {
                float f0, f1, f2, f3, f4, f5, f6, f7;
                unpack2(acc[m * 4 + 0], f0, f1);
                unpack2(acc[m * 4 + 1], f2, f3);
                unpack2(acc[m * 4 + 2], f4, f5);
                unpack2(acc[m * 4 + 3], f6, f7);
                uint4 pk;
                __half2* ph = (__half2*)&pk;
                ph[0] = __floats2half2_rn(f0, f1);
                ph[1] = __floats2half2_rn(f2, f3);
                ph[2] = __floats2half2_rn(f4, f5);
                ph[3] = __floats2half2_rn(f6, f7);
                *(uint4*)(Out + (size_t)r * HID + col0 + tx8) = pk;
            }
        }
    } else {
        const float4 cA = *(const float4*)&g_c0[col0 + tx8];
        const float4 cB = *(const float4*)&g_c0[col0 + tx8 + 4];
        #pragma unroll
        for (int m = 0; m < 8; m++) {
            int r = row0 + ty8 + m;
            if (r < N_NODES) {
                float4 o0, o1;
                unpack2(acc[m * 4 + 0], o0.x, o0.y);
                unpack2(acc[m * 4 + 1], o0.z, o0.w);
                unpack2(acc[m * 4 + 2], o1.x, o1.y);
                unpack2(acc[m * 4 + 3], o1.z, o1.w);
                o0.x += cA.x; o0.y += cA.y; o0.z += cA.z; o0.w += cA.w;
                o1.x += cB.x; o1.y += cB.y; o1.z += cB.z; o1.w += cB.w;
                float* dst = out + (size_t)r * HID + col0 + tx8;
                __stcs((float4*)dst, o0);
                __stcs((float4*)(dst + 4), o1);
            }
        }
    }
}

// ---------------------------------------------------------------------------
// Edge rows (measured-best R13 version): one warp per edge pair, LDG.256
// evict_last gathers, smem-swizzled transpose to contiguous 512B store slabs.
// ---------------------------------------------------------------------------
__global__ void __launch_bounds__(256)
edge_kernel(const int* __restrict__ ei, float* __restrict__ out) {
    __shared__ float4 sbuf[8][128];
    const int tid = threadIdx.x;
    const int w = tid >> 5, c = tid & 31;
    const int p = blockIdx.x * 8 + w;
    const int e0 = p * 2, e1 = e0 + 1;

    int s0, d0, s1, d1;
    if (g_idx64) {
        s0 = ei[2 * (size_t)e0];
        d0 = ei[2 * ((size_t)N_EDGES + e0)];
        s1 = ei[2 * (size_t)e1];
        d1 = ei[2 * ((size_t)N_EDGES + e1)];
    } else {
        s0 = ei[e0];  d0 = ei[N_EDGES + e0];
        s1 = ei[e1];  d1 = ei[N_EDGES + e1];
    }

    float4 c1r[4];
    #pragma unroll
    for (int j = 0; j < 4; j++)
        c1r[j] = __ldg((const float4*)g_c1 + c * 4 + j);

    #pragma unroll
    for (int half = 0; half < 2; half++) {
        const int e = half ? e1 : e0;
        const int sI = half ? s1 : s0;
        const int dI = half ? d1 : d0;

        U8 u = ldg256_el(g_Uh + (size_t)sI * HID + c * 16);
        U8 v = ldg256_el(g_Vh + (size_t)dI * HID + c * 16);

        #pragma unroll
        for (int j = 0; j < 4; j++) {
            float2 ua = __half22float2(*(const __half2*)&u.r[j * 2]);
            float2 ub = __half22float2(*(const __half2*)&u.r[j * 2 + 1]);
            float2 va = __half22float2(*(const __half2*)&v.r[j * 2]);
            float2 vb = __half22float2(*(const __half2*)&v.r[j * 2 + 1]);
            float4 o;
            o.x = ua.x + va.x + c1r[j].x;  o.y = ua.y + va.y + c1r[j].y;
            o.z = ub.x + vb.x + c1r[j].z;  o.w = ub.y + vb.y + c1r[j].w;
            int g = c * 4 + j;
            sbuf[w][g ^ (g >> 2)] = o;
        }
        __syncwarp();

        float4* dst = (float4*)(out + (size_t)(N_NODES + e) * HID);
        #pragma unroll
        for (int q = 0; q < 4; q++) {
            int h = q * 32 + c;
            float4 val = sbuf[w][h ^ (h >> 2)];
            __stcs(dst + h, val);
        }
        __syncwarp();
    }
}

// ---------------------------------------------------------------------------
static bool g_attr_set = false;

extern "C" void kernel_launch(void* const* d_in, const int* in_sizes, int n_in,
                              void* d_out, int out_size) {
    const void* ptr[7] = {d_in[0], d_in[1], d_in[2], d_in[3], d_in[4], d_in[5], d_in[6]};
    const int want[7] = {6400000, 3200000, 128, 256, 196608, 512, 1600000};
    const void* mapped[7];
    for (int w = 0; w < 7; w++) {
        mapped[w] = ptr[w < n_in ? w : 0];
        for (int i = 0; i < n_in && i < 7; i++)
            if (in_sizes[i] == want[w]) { mapped[w] = ptr[i]; break; }
    }
    const float* nf  = (const float*)mapped[0];
    const float* pe  = (const float*)mapped[1];
    const float* ef  = (const float*)mapped[2];
    const float* tte = (const float*)mapped[3];
    const float* W   = (const float*)mapped[4];
    const float* b   = (const float*)mapped[5];
    const int*   ei  = (const int*)mapped[6];
    float* out = (float*)d_out;

    if (!g_attr_set) {
        cudaStreamCaptureStatus cs = cudaStreamCaptureStatusNone;
        cudaStreamIsCapturing((cudaStream_t)0, &cs);
        if (cs == cudaStreamCaptureStatusNone) {
            cudaFuncSetAttribute(gemm_kernel,
                                 cudaFuncAttributeMaxDynamicSharedMemorySize,
                                 SMEM_BYTES);
            g_attr_set = true;
        }
    }

    prep_kernel<<<49, 256>>>(ef, tte, W, b, ei);
    transpose_kernel<<<dim3(1563, 6), 256>>>(nf, pe);
    gemm_kernel<<<GRID_GEMM, 256, SMEM_BYTES>>>(W, out);
    edge_kernel<<<NB_EDGE, 256>>>(ei, out);
}